// round 1
// baseline (speedup 1.0000x reference)
#include <cuda_runtime.h>

// Problem constants
#define B_   16
#define H_   64
#define W_   64
#define C_   256
#define KE   4
#define F_   256
#define HW_  (H_ * W_)
#define PER_B (9 * C_ * F_)          // 589824 elements of combined kernel per sample

// Scratch (device globals: allocation-free)
__device__ float g_partial[B_ * 16 * C_];    // partial pooling sums
__device__ float g_att[B_ * KE];             // softmax routing weights
__device__ float g_bias[B_ * F_];            // per-sample output bias
__device__ float g_ker[B_ * PER_B];          // per-sample combined conv kernel (37.7 MB)

// ---------------------------------------------------------------------------
// 1) Partial pooling: each block sums a 256-row chunk of HW for one sample.
//    grid (16, B_), 256 threads; thread t owns channel t (coalesced loads).
// ---------------------------------------------------------------------------
__global__ void pool_kernel(const float* __restrict__ in) {
    int b = blockIdx.y;
    int s = blockIdx.x;           // hw chunk 0..15 (256 rows each)
    int c = threadIdx.x;          // channel
    const float* p = in + ((long)b * HW_ + s * 256) * C_ + c;
    float sum = 0.f;
#pragma unroll 4
    for (int i = 0; i < 256; i++) sum += p[i * C_];
    g_partial[(b * 16 + s) * C_ + c] = sum;
}

// ---------------------------------------------------------------------------
// 2) Routing: reduce partials -> pool -> MLP -> softmax -> att, bias.
//    grid B_, 256 threads.
// ---------------------------------------------------------------------------
__global__ void route_kernel(const float* __restrict__ w1, const float* __restrict__ b1,
                             const float* __restrict__ w2, const float* __restrict__ b2,
                             const float* __restrict__ biases) {
    __shared__ float pool[C_];
    __shared__ float a1[64];
    __shared__ float att[KE];

    int b = blockIdx.x;
    int t = threadIdx.x;

    float sum = 0.f;
#pragma unroll
    for (int s = 0; s < 16; s++) sum += g_partial[(b * 16 + s) * C_ + t];
    pool[t] = sum * (1.0f / (float)HW_);
    __syncthreads();

    if (t < 64) {
        float v = b1[t];
#pragma unroll 4
        for (int c = 0; c < C_; c++) v += pool[c] * w1[c * 64 + t];
        a1[t] = fmaxf(v, 0.f);
    }
    __syncthreads();

    if (t < KE) {
        float v = b2[t];
#pragma unroll
        for (int j = 0; j < 64; j++) v += a1[j] * w2[j * KE + t];
        att[t] = v;  // logits for now
    }
    __syncthreads();

    if (t == 0) {
        float m = att[0];
        for (int e = 1; e < KE; e++) m = fmaxf(m, att[e]);
        float ex[KE];
        float s2 = 0.f;
        for (int e = 0; e < KE; e++) { ex[e] = expf(att[e] - m); s2 += ex[e]; }
        float inv = 1.0f / s2;
        for (int e = 0; e < KE; e++) {
            att[e] = ex[e] * inv;
            g_att[b * KE + e] = att[e];
        }
    }
    __syncthreads();

    // per-sample output bias: bias[b,f] = sum_e att[e] * biases[e,f]
    float bv = 0.f;
#pragma unroll
    for (int e = 0; e < KE; e++) bv += att[e] * biases[e * F_ + t];
    g_bias[b * F_ + t] = bv;
}

// ---------------------------------------------------------------------------
// 3) Combine expert kernels per sample: g_ker[b] = sum_e att[b,e]*kernels[e].
//    float4 per thread; grid covers B_*PER_B/4 float4 slots.
// ---------------------------------------------------------------------------
__global__ void combine_kernel(const float* __restrict__ kernels) {
    long i4 = ((long)blockIdx.x * blockDim.x + threadIdx.x) * 4;
    int b = (int)(i4 / PER_B);
    long off = i4 - (long)b * PER_B;

    float a0 = g_att[b * KE + 0];
    float a1v = g_att[b * KE + 1];
    float a2 = g_att[b * KE + 2];
    float a3 = g_att[b * KE + 3];

    float4 k0 = *(const float4*)(kernels + 0L * PER_B + off);
    float4 k1 = *(const float4*)(kernels + 1L * PER_B + off);
    float4 k2 = *(const float4*)(kernels + 2L * PER_B + off);
    float4 k3 = *(const float4*)(kernels + 3L * PER_B + off);

    float4 r;
    r.x = a0 * k0.x + a1v * k1.x + a2 * k2.x + a3 * k3.x;
    r.y = a0 * k0.y + a1v * k1.y + a2 * k2.y + a3 * k3.y;
    r.z = a0 * k0.z + a1v * k1.z + a2 * k2.z + a3 * k3.z;
    r.w = a0 * k0.w + a1v * k1.w + a2 * k2.w + a3 * k3.w;

    *(float4*)(g_ker + (long)b * PER_B + off) = r;
}

// ---------------------------------------------------------------------------
// 4) Implicit-GEMM conv. Per sample b:
//      out[4096, 256] = patches[4096, 2304] @ g_ker[b] [2304, 256]
//    K ordered as (tap r 0..8) x (c 0..255); BK=32 so each K-tile has a fixed
//    tap -> uniform zero-padding per A row, aligned float4 global loads.
//    BM=128, BN=64, BK=32, 256 threads, 8x4 accum per thread.
// ---------------------------------------------------------------------------
#define BM 128
#define BN 64
#define BK 32
#define APAD 36   // row stride for As (floats): keeps STS conflicts low, 16B aligned

__global__ __launch_bounds__(256, 2)
void conv_kernel(const float* __restrict__ in, float* __restrict__ out) {
    __shared__ float As[BM][APAD];   // As[m][kk]
    __shared__ float Bs[BK][BN];     // Bs[kk][n]

    int b  = blockIdx.z;
    int m0 = blockIdx.x * BM;
    int n0 = blockIdx.y * BN;
    int tid = threadIdx.x;
    int tx = tid & 15;   // n direction: 16 * 4 = 64
    int ty = tid >> 4;   // m direction: 16 * 8 = 128

    const float* inb  = in + (long)b * HW_ * C_;
    const float* kerb = g_ker + (long)b * PER_B;

    float acc[8][4];
#pragma unroll
    for (int i = 0; i < 8; i++)
#pragma unroll
        for (int j = 0; j < 4; j++) acc[i][j] = 0.f;

    int arow = tid >> 3;          // 0..31
    int ac4  = (tid & 7) << 2;    // 0,4,...,28

    for (int kt = 0; kt < 72; kt++) {
        int r = kt >> 3;                  // tap 0..8
        int ky = r / 3 - 1;
        int kx = r % 3 - 1;
        int cbase = (kt & 7) << 5;        // 0..224

        // ---- load A tile: 128 rows x 32 cols, float4 per slot ----
#pragma unroll
        for (int i = 0; i < 4; i++) {
            int m = arow + i * 32;
            int hw = m0 + m;
            int h = hw >> 6, w = hw & 63;
            int ih = h + ky, iw = w + kx;
            float4 v = make_float4(0.f, 0.f, 0.f, 0.f);
            if ((unsigned)ih < H_ && (unsigned)iw < W_)
                v = *(const float4*)(inb + ((ih << 6) + iw) * C_ + cbase + ac4);
            *(float4*)(&As[m][ac4]) = v;
        }

        // ---- load B tile: 32 x 64, 512 float4 slots ----
#pragma unroll
        for (int i = 0; i < 2; i++) {
            int s = tid + i * 256;
            int kk = s >> 4;
            int n4 = (s & 15) << 2;
            float4 v = *(const float4*)(kerb + (long)(r * C_ + cbase + kk) * F_ + n0 + n4);
            *(float4*)(&Bs[kk][n4]) = v;
        }
        __syncthreads();

        // ---- compute ----
#pragma unroll
        for (int kk = 0; kk < BK; kk++) {
            float4 bv = *(const float4*)(&Bs[kk][tx << 2]);
            float bf[4] = {bv.x, bv.y, bv.z, bv.w};
            float af[8];
#pragma unroll
            for (int i = 0; i < 8; i++) af[i] = As[(ty << 3) + i][kk];
#pragma unroll
            for (int i = 0; i < 8; i++)
#pragma unroll
                for (int j = 0; j < 4; j++) acc[i][j] += af[i] * bf[j];
        }
        __syncthreads();
    }

    // ---- epilogue: add per-sample bias, float4 stores ----
    float4 bias = *(const float4*)(g_bias + b * F_ + n0 + (tx << 2));
#pragma unroll
    for (int i = 0; i < 8; i++) {
        int m = m0 + (ty << 3) + i;
        float4 o;
        o.x = acc[i][0] + bias.x;
        o.y = acc[i][1] + bias.y;
        o.z = acc[i][2] + bias.z;
        o.w = acc[i][3] + bias.w;
        *(float4*)(out + ((long)b * HW_ + m) * F_ + n0 + (tx << 2)) = o;
    }
}

// ---------------------------------------------------------------------------
// Launch
// ---------------------------------------------------------------------------
extern "C" void kernel_launch(void* const* d_in, const int* in_sizes, int n_in,
                              void* d_out, int out_size) {
    const float* inputs  = (const float*)d_in[0];  // [B,H,W,C]
    const float* kernels = (const float*)d_in[1];  // [KE,3,3,C,F]
    const float* biases  = (const float*)d_in[2];  // [KE,F]
    const float* w1      = (const float*)d_in[3];  // [C, C/4]
    const float* b1      = (const float*)d_in[4];  // [C/4]
    const float* w2      = (const float*)d_in[5];  // [C/4, KE]
    const float* b2      = (const float*)d_in[6];  // [KE]
    float* out = (float*)d_out;                    // [B,H,W,F]

    // 1) pooling partials
    pool_kernel<<<dim3(16, B_), 256>>>(inputs);
    // 2) routing (pool reduce + MLP + softmax + bias combine)
    route_kernel<<<B_, 256>>>(w1, b1, w2, b2, biases);
    // 3) combined per-sample kernels
    {
        long total4 = (long)B_ * PER_B / 4;        // 2,359,296
        int blocks = (int)(total4 / 256);          // 9216
        combine_kernel<<<blocks, 256>>>(kernels);
    }
    // 4) implicit-GEMM conv
    conv_kernel<<<dim3(HW_ / BM, F_ / BN, B_), 256>>>(inputs, out);
}

// round 3
// speedup vs baseline: 5.4512x; 5.4512x over previous
#include <cuda_runtime.h>
#include <cuda_fp16.h>
#include <cstdint>

// ---------------------------------------------------------------------------
// Problem constants
// ---------------------------------------------------------------------------
#define B_   16
#define H_   64
#define W_   64
#define C_   256
#define KE   4
#define F_   256
#define HW_  (H_ * W_)
#define KTOT 2304                    // 9 * C_
#define PER_E (9 * C_ * F_)

// GEMM tiling
#define BM 128
#define BN 128
#define BK 32
#define NITER 72                     // KTOT / BK
#define STAGES 4
#define A_ROW_BYTES 80               // 64B data + 16B pad (conflict-free ldmatrix)
#define A_STAGE (BM * A_ROW_BYTES)   // 10240
#define B_STAGE (BK * BN * 2)        // 8192
#define STG_BYTES (A_STAGE + B_STAGE)        // 18432
#define SMEM_TOTAL (STAGES * STG_BYTES)      // 73728

// ---------------------------------------------------------------------------
// Device scratch
// ---------------------------------------------------------------------------
__device__ float g_partial[B_ * 16 * C_];
__device__ float g_att[B_ * KE];
__device__ float g_bias[B_ * F_];
__device__ __align__(16) __half g_in_h[B_ * HW_ * C_];   // fp16 inputs
__device__ __align__(16) __half g_w[B_ * KTOT * F_];     // fp16 combined kernels [b][k][f]

// ---------------------------------------------------------------------------
// PTX helpers
// ---------------------------------------------------------------------------
__device__ __forceinline__ uint32_t smem_u32(const void* p) {
    uint32_t a;
    asm("{ .reg .u64 t; cvta.to.shared.u64 t, %1; cvt.u32.u64 %0, t; }" : "=r"(a) : "l"(p));
    return a;
}
#define CP_ASYNC16(dst, src, ok) \
    asm volatile("{\n\t.reg .pred p;\n\t.reg .b32 sz;\n\tsetp.ne.u32 p, %2, 0;\n\tselp.b32 sz, 16, 0, p;\n\tcp.async.cg.shared.global [%0], [%1], 16, sz;\n\t}" \
        :: "r"(dst), "l"(src), "r"((unsigned)(ok)) : "memory")
#define CP_COMMIT() asm volatile("cp.async.commit_group;" ::: "memory")
#define CP_WAIT2()  asm volatile("cp.async.wait_group 2;" ::: "memory")

#define LDSM_X4(r0, r1, r2, r3, a) \
    asm volatile("ldmatrix.sync.aligned.m8n8.x4.shared.b16 {%0,%1,%2,%3}, [%4];" \
        : "=r"(r0), "=r"(r1), "=r"(r2), "=r"(r3) : "r"(a))
#define LDSM_X4_T(r0, r1, r2, r3, a) \
    asm volatile("ldmatrix.sync.aligned.m8n8.x4.trans.shared.b16 {%0,%1,%2,%3}, [%4];" \
        : "=r"(r0), "=r"(r1), "=r"(r2), "=r"(r3) : "r"(a))

#define MMA16816(c0, c1, c2, c3, a0, a1, a2, a3, b0, b1) \
    asm volatile("mma.sync.aligned.m16n8k16.row.col.f32.f16.f16.f32 " \
        "{%0,%1,%2,%3}, {%4,%5,%6,%7}, {%8,%9}, {%0,%1,%2,%3};" \
        : "+f"(c0), "+f"(c1), "+f"(c2), "+f"(c3) \
        : "r"(a0), "r"(a1), "r"(a2), "r"(a3), "r"(b0), "r"(b1))

// ---------------------------------------------------------------------------
// 1) Partial pooling
// ---------------------------------------------------------------------------
__global__ void pool_kernel(const float* __restrict__ in) {
    int b = blockIdx.y, s = blockIdx.x, c = threadIdx.x;
    const float* p = in + ((long)b * HW_ + s * 256) * C_ + c;
    float sum = 0.f;
#pragma unroll 4
    for (int i = 0; i < 256; i++) sum += p[i * C_];
    g_partial[(b * 16 + s) * C_ + c] = sum;
}

// ---------------------------------------------------------------------------
// 2) Routing
// ---------------------------------------------------------------------------
__global__ void route_kernel(const float* __restrict__ w1, const float* __restrict__ b1,
                             const float* __restrict__ w2, const float* __restrict__ b2,
                             const float* __restrict__ biases) {
    __shared__ float pool[C_];
    __shared__ float a1[64];
    __shared__ float att[KE];
    int b = blockIdx.x, t = threadIdx.x;

    float sum = 0.f;
#pragma unroll
    for (int s = 0; s < 16; s++) sum += g_partial[(b * 16 + s) * C_ + t];
    pool[t] = sum * (1.0f / (float)HW_);
    __syncthreads();

    if (t < 64) {
        float v = b1[t];
#pragma unroll 4
        for (int c = 0; c < C_; c++) v += pool[c] * w1[c * 64 + t];
        a1[t] = fmaxf(v, 0.f);
    }
    __syncthreads();
    if (t < KE) {
        float v = b2[t];
#pragma unroll
        for (int j = 0; j < 64; j++) v += a1[j] * w2[j * KE + t];
        att[t] = v;
    }
    __syncthreads();
    if (t == 0) {
        float m = att[0];
        for (int e = 1; e < KE; e++) m = fmaxf(m, att[e]);
        float ex[KE], s2 = 0.f;
        for (int e = 0; e < KE; e++) { ex[e] = expf(att[e] - m); s2 += ex[e]; }
        float inv = 1.0f / s2;
        for (int e = 0; e < KE; e++) { att[e] = ex[e] * inv; g_att[b * KE + e] = att[e]; }
    }
    __syncthreads();
    float bv = 0.f;
#pragma unroll
    for (int e = 0; e < KE; e++) bv += att[e] * biases[e * F_ + t];
    g_bias[b * F_ + t] = bv;
}

// ---------------------------------------------------------------------------
// 3) Convert inputs to fp16 (8 elements / thread)
// ---------------------------------------------------------------------------
__global__ void tohalf_kernel(const float* __restrict__ in) {
    long i = ((long)blockIdx.x * blockDim.x + threadIdx.x) * 8;
    float4 v0 = *(const float4*)(in + i);
    float4 v1 = *(const float4*)(in + i + 4);
    __half2 h[4];
    h[0] = __floats2half2_rn(v0.x, v0.y);
    h[1] = __floats2half2_rn(v0.z, v0.w);
    h[2] = __floats2half2_rn(v1.x, v1.y);
    h[3] = __floats2half2_rn(v1.z, v1.w);
    *(uint4*)(g_in_h + i) = *(uint4*)h;
}

// ---------------------------------------------------------------------------
// 4) Combine experts -> fp16 [b][k][f] (natural layout; no transpose needed)
// ---------------------------------------------------------------------------
__global__ void combine_h_kernel(const float* __restrict__ kernels) {
    int b = blockIdx.y;
    long off = ((long)blockIdx.x * blockDim.x + threadIdx.x) * 4;
    float a0 = g_att[b * KE + 0], a1v = g_att[b * KE + 1];
    float a2 = g_att[b * KE + 2], a3 = g_att[b * KE + 3];
    float4 k0 = *(const float4*)(kernels + 0L * PER_E + off);
    float4 k1 = *(const float4*)(kernels + 1L * PER_E + off);
    float4 k2 = *(const float4*)(kernels + 2L * PER_E + off);
    float4 k3 = *(const float4*)(kernels + 3L * PER_E + off);
    float rx = a0 * k0.x + a1v * k1.x + a2 * k2.x + a3 * k3.x;
    float ry = a0 * k0.y + a1v * k1.y + a2 * k2.y + a3 * k3.y;
    float rz = a0 * k0.z + a1v * k1.z + a2 * k2.z + a3 * k3.z;
    float rw = a0 * k0.w + a1v * k1.w + a2 * k2.w + a3 * k3.w;
    __half2 h[2];
    h[0] = __floats2half2_rn(rx, ry);
    h[1] = __floats2half2_rn(rz, rw);
    *(uint2*)(g_w + (long)b * PER_E + off) = *(uint2*)h;
}

// ---------------------------------------------------------------------------
// 5) Implicit-GEMM conv with mma.sync (fp16 in, fp32 acc).
//    out[b][m,n] = sum_k A[b][m,k] * W[b][k,n];  k = tap r * 256 + c.
// ---------------------------------------------------------------------------
__global__ __launch_bounds__(256, 2)
void conv_mma_kernel(float* __restrict__ out) {
    extern __shared__ __align__(1024) char smem[];
    uint32_t sb = smem_u32(smem);
    int tid = threadIdx.x;
    int lane = tid & 31, wid = tid >> 5;
    int wm = wid >> 2, wn = wid & 3;          // 2 x 4 warp grid
    int b = blockIdx.z;
    int m0 = blockIdx.x * BM;
    int n0 = blockIdx.y * BN;

    float acc[4][4][4];
#pragma unroll
    for (int i = 0; i < 4; i++)
#pragma unroll
        for (int j = 0; j < 4; j++)
#pragma unroll
            for (int k = 0; k < 4; k++) acc[i][j][k] = 0.f;

    const long inb = (long)b * HW_ * C_;
    const long wbb = (long)b * (long)KTOT * F_;

    // A load mapping: thread -> 2 contiguous 16B chunks (row, segs)
    const int a_row = tid >> 1;               // 0..127
    const int a_seg = (tid & 1) * 2;          // 0 or 2
    // B load mapping: thread -> chunks tid, tid+256 (row kk, chunk)
    // stage loader
    auto load_stage = [&](int stage, int kt) {
        uint32_t st = sb + stage * STG_BYTES;
        int r = kt >> 3;
        int cbase = (kt & 7) << 5;
        int ky = r / 3 - 1, kx = r % 3 - 1;
        // A: 128 rows x 32 halves (64B)
        {
            int m = m0 + a_row;
            int h = m >> 6, w = m & 63;
            int ih = h + ky, iw = w + kx;
            unsigned ok = ((unsigned)ih < H_) & ((unsigned)iw < W_);
            const __half* src = g_in_h + (ok ? (inb + ((long)((ih << 6) + iw)) * C_ + cbase + a_seg * 8) : 0);
            uint32_t d = st + a_row * A_ROW_BYTES + a_seg * 16;
            CP_ASYNC16(d, src, ok);
            CP_ASYNC16(d + 16, src + 8, ok);
        }
        // B: 32 rows x 128 halves (256B), swizzle chunk ^ (kk & 7)
#pragma unroll
        for (int i = 0; i < 2; i++) {
            int cid = tid + i * 256;
            int kk = cid >> 4;
            int ch = cid & 15;
            const __half* src = g_w + wbb + ((long)(r * C_ + cbase + kk)) * F_ + n0 + ch * 8;
            uint32_t d = st + A_STAGE + kk * 256 + ((ch ^ (kk & 7)) << 4);
            CP_ASYNC16(d, src, 1u);
        }
    };

    // prefetch 3 stages
#pragma unroll
    for (int s = 0; s < 3; s++) { load_stage(s, s); CP_COMMIT(); }

    for (int kt = 0; kt < NITER; kt++) {
        CP_WAIT2();
        __syncthreads();

        if (kt + 3 < NITER) load_stage((kt + 3) & 3, kt + 3);
        CP_COMMIT();

        uint32_t stA = sb + ((kt & 3) * STG_BYTES);
        uint32_t stB = stA + A_STAGE;

#pragma unroll
        for (int ks = 0; ks < 2; ks++) {
            // A fragments: 4 m-tiles of 16, k16 slice ks
            uint32_t a[4][4];
#pragma unroll
            for (int mt = 0; mt < 4; mt++) {
                int row = wm * 64 + mt * 16 + ((lane >> 3) & 1) * 8 + (lane & 7);
                int kc = ks * 2 + (lane >> 4);
                LDSM_X4(a[mt][0], a[mt][1], a[mt][2], a[mt][3],
                        stA + row * A_ROW_BYTES + kc * 16);
            }
            // B fragments: 4 n8-groups via 2 ldmatrix.x4.trans
            uint32_t br[2][4];
#pragma unroll
            for (int p = 0; p < 2; p++) {
                int kkl = ks * 16 + ((lane >> 3) & 1) * 8 + (lane & 7);
                int nch = wn * 4 + p * 2 + (lane >> 4);
                LDSM_X4_T(br[p][0], br[p][1], br[p][2], br[p][3],
                          stB + kkl * 256 + ((nch ^ (kkl & 7)) << 4));
            }
#pragma unroll
            for (int mt = 0; mt < 4; mt++) {
#pragma unroll
                for (int ng = 0; ng < 4; ng++) {
                    uint32_t b0 = br[ng >> 1][(ng & 1) * 2];
                    uint32_t b1 = br[ng >> 1][(ng & 1) * 2 + 1];
                    MMA16816(acc[mt][ng][0], acc[mt][ng][1], acc[mt][ng][2], acc[mt][ng][3],
                             a[mt][0], a[mt][1], a[mt][2], a[mt][3], b0, b1);
                }
            }
        }
    }

    // epilogue: bias + store
    float2 bias[4];
#pragma unroll
    for (int ng = 0; ng < 4; ng++) {
        int col = n0 + wn * 32 + ng * 8 + (lane & 3) * 2;
        bias[ng] = *(const float2*)(g_bias + b * F_ + col);
    }
#pragma unroll
    for (int mt = 0; mt < 4; mt++) {
        int row0 = m0 + wm * 64 + mt * 16 + (lane >> 2);
        float* p0 = out + ((long)b * HW_ + row0) * F_;
        float* p1 = p0 + 8L * F_;
#pragma unroll
        for (int ng = 0; ng < 4; ng++) {
            int col = n0 + wn * 32 + ng * 8 + (lane & 3) * 2;
            float2 v0 = make_float2(acc[mt][ng][0] + bias[ng].x, acc[mt][ng][1] + bias[ng].y);
            float2 v1 = make_float2(acc[mt][ng][2] + bias[ng].x, acc[mt][ng][3] + bias[ng].y);
            *(float2*)(p0 + col) = v0;
            *(float2*)(p1 + col) = v1;
        }
    }
}

// ---------------------------------------------------------------------------
// Launch
// ---------------------------------------------------------------------------
extern "C" void kernel_launch(void* const* d_in, const int* in_sizes, int n_in,
                              void* d_out, int out_size) {
    const float* inputs  = (const float*)d_in[0];
    const float* kernels = (const float*)d_in[1];
    const float* biases  = (const float*)d_in[2];
    const float* w1      = (const float*)d_in[3];
    const float* b1      = (const float*)d_in[4];
    const float* w2      = (const float*)d_in[5];
    const float* b2      = (const float*)d_in[6];
    float* out = (float*)d_out;

    static int smem_set = 0;
    if (!smem_set) {
        cudaFuncSetAttribute(conv_mma_kernel, cudaFuncAttributeMaxDynamicSharedMemorySize, SMEM_TOTAL);
        smem_set = 1;
    }

    pool_kernel<<<dim3(16, B_), 256>>>(inputs);
    route_kernel<<<B_, 256>>>(w1, b1, w2, b2, biases);
    tohalf_kernel<<<(B_ * HW_ * C_) / 8 / 256, 256>>>(inputs);
    combine_h_kernel<<<dim3(PER_E / 4 / 256, B_), 256>>>(kernels);
    conv_mma_kernel<<<dim3(HW_ / BM, F_ / BN, B_), 256, SMEM_TOTAL>>>(out);
}